// round 15
// baseline (speedup 1.0000x reference)
#include <cuda_runtime.h>

#define NN 100000
#define NE 1600000
#define CIN 128
#define CH  128
#define CO  64

// ---------------- scratch (device globals: allocation-free) ----------------
__device__ __align__(16) float g_u1[(size_t)NN * CH];    // (x@W1)*dinv[row]
__device__ __align__(16) float g_agg1[(size_t)NN * CH];  // layer-1 accumulator
__device__ __align__(16) float g_u2[(size_t)NN * CO];    // (x2@W2)*dinv[row]
__device__ int   g_deg[NN];
__device__ float g_dinv[NN];
__device__ int   g_is64;   // 1 if edge_index is int64, 0 if int32

// ---------------- init: zero degrees + detect edge dtype -------------------
__global__ void k_init(const int* __restrict__ ei) {
    int i = blockIdx.x * blockDim.x + threadIdx.x;
    if (i < NN) g_deg[i] = 0;
    if (blockIdx.x == 0) {
        __shared__ int s_nz;
        if (threadIdx.x == 0) s_nz = 0;
        __syncthreads();
        // If int64 with values in [0,100000): every odd int32 word is 0.
        // If int32: odd words are random edge ids (P(all 256 == 0) ~ 0).
        if (ei[2 * threadIdx.x + 1] != 0) atomicOr(&s_nz, 1);
        __syncthreads();
        if (threadIdx.x == 0) g_is64 = s_nz ? 0 : 1;
    }
}

__device__ __forceinline__ int edge_val(const int* ei, int idx, int is64) {
    if (is64) return (int)((const long long*)ei)[idx];
    return ei[idx];
}

// ---------------- degree histogram over dst ---------------------------------
__global__ void k_deg(const int* __restrict__ ei) {
    int e = blockIdx.x * blockDim.x + threadIdx.x;
    if (e >= NE) return;
    int is64 = g_is64;
    int d = edge_val(ei, NE + e, is64);
    atomicAdd(&g_deg[d], 1);
}

__global__ void k_dinv() {
    int i = blockIdx.x * blockDim.x + threadIdx.x;
    if (i < NN) g_dinv[i] = rsqrtf((float)(g_deg[i] + 2));  // +2 self loops
}

// ---------------- GEMM1: u1 = (x @ W1) * dinv ; agg1 = 2*u1 ----------------
// 64 rows x 128 cols per block, 256 threads, thread = 8 rows x 4 cols.
__global__ __launch_bounds__(256) void k_gemm1(const float* __restrict__ x,
                                               const float* __restrict__ W) {
    __shared__ float As[16][64];    // k-major (transposed) A tile
    __shared__ float Bs[16][128];
    int row0 = blockIdx.x * 64;
    int tid  = threadIdx.x;
    int warp = tid >> 5, lane = tid & 31;

    float acc[8][4];
#pragma unroll
    for (int r = 0; r < 8; r++)
#pragma unroll
        for (int c = 0; c < 4; c++) acc[r][c] = 0.f;

    for (int k0 = 0; k0 < CIN; k0 += 16) {
        {   // A tile: 64 rows x 16 k
            int r = tid >> 2, kk4 = (tid & 3) << 2;
            int gr = row0 + r;
            float4 a = make_float4(0.f, 0.f, 0.f, 0.f);
            if (gr < NN) a = *(const float4*)(x + (size_t)gr * CIN + k0 + kk4);
            As[kk4 + 0][r] = a.x; As[kk4 + 1][r] = a.y;
            As[kk4 + 2][r] = a.z; As[kk4 + 3][r] = a.w;
        }
#pragma unroll
        for (int t = 0; t < 2; t++) {   // B tile: 16 k x 128 cols
            int fi = tid + t * 256;
            int kk = fi >> 5, c4 = (fi & 31) << 2;
            *(float4*)&Bs[kk][c4] = *(const float4*)(W + (size_t)(k0 + kk) * CH + c4);
        }
        __syncthreads();
#pragma unroll
        for (int kk = 0; kk < 16; kk++) {
            float4 a0 = *(const float4*)&As[kk][warp * 8];
            float4 a1 = *(const float4*)&As[kk][warp * 8 + 4];
            float4 b  = *(const float4*)&Bs[kk][lane * 4];
            float av[8] = {a0.x, a0.y, a0.z, a0.w, a1.x, a1.y, a1.z, a1.w};
#pragma unroll
            for (int r = 0; r < 8; r++) {
                acc[r][0] += av[r] * b.x;
                acc[r][1] += av[r] * b.y;
                acc[r][2] += av[r] * b.z;
                acc[r][3] += av[r] * b.w;
            }
        }
        __syncthreads();
    }
#pragma unroll
    for (int r = 0; r < 8; r++) {
        int gr = row0 + warp * 8 + r;
        if (gr >= NN) continue;
        float di = g_dinv[gr];
        float4 u = make_float4(acc[r][0] * di, acc[r][1] * di,
                               acc[r][2] * di, acc[r][3] * di);
        size_t off = (size_t)gr * CH + lane * 4;
        *(float4*)(g_u1 + off)   = u;
        *(float4*)(g_agg1 + off) = make_float4(2.f * u.x, 2.f * u.y,
                                               2.f * u.z, 2.f * u.w);
    }
}

// ---------------- scatter layer 1: agg1[d] += u1[s] (one warp / edge) ------
__global__ __launch_bounds__(256) void k_scatter1(const int* __restrict__ ei) {
    int gw = (blockIdx.x * 256 + threadIdx.x) >> 5;
    if (gw >= NE) return;
    int lane = threadIdx.x & 31;
    int is64 = g_is64;
    int s = edge_val(ei, gw, is64);
    int d = edge_val(ei, NE + gw, is64);
    const float4 u = *(const float4*)(g_u1 + (size_t)s * CH + lane * 4);
    float* p = g_agg1 + (size_t)d * CH + lane * 4;
    asm volatile("red.global.add.v4.f32 [%0], {%1,%2,%3,%4};"
                 :: "l"(p), "f"(u.x), "f"(u.y), "f"(u.z), "f"(u.w)
                 : "memory");
}

// ---------------- GEMM2: x2 = relu(dinv*agg1 + b1) fused into A-load -------
// u2 = (x2 @ W2) * dinv ; agg2(=d_out) = 2*u2.
// 64 rows x 64 cols per block, 128 threads, thread = 8 rows x 4 cols.
__global__ __launch_bounds__(128) void k_gemm2(const float* __restrict__ b1,
                                               const float* __restrict__ W2,
                                               float* __restrict__ agg2) {
    __shared__ float As[16][64];
    __shared__ float Bs[16][64];
    int row0 = blockIdx.x * 64;
    int tid  = threadIdx.x;
    int warp = tid >> 5, lane = tid & 31;
    int sub = lane >> 4, cg = lane & 15;

    float acc[8][4];
#pragma unroll
    for (int r = 0; r < 8; r++)
#pragma unroll
        for (int c = 0; c < 4; c++) acc[r][c] = 0.f;

    for (int k0 = 0; k0 < CH; k0 += 16) {
        {   // A tile with fused relu(dinv*agg1 + b1)
            int r = tid >> 1, kh = (tid & 1) << 3;
            int gr = row0 + r;
            float di = (gr < NN) ? g_dinv[gr] : 0.f;
#pragma unroll
            for (int t = 0; t < 2; t++) {
                int kk = kh + t * 4;
                float4 ag = make_float4(0.f, 0.f, 0.f, 0.f);
                if (gr < NN) ag = *(const float4*)(g_agg1 + (size_t)gr * CH + k0 + kk);
                float4 bb = *(const float4*)(b1 + k0 + kk);
                As[kk + 0][r] = fmaxf(di * ag.x + bb.x, 0.f);
                As[kk + 1][r] = fmaxf(di * ag.y + bb.y, 0.f);
                As[kk + 2][r] = fmaxf(di * ag.z + bb.z, 0.f);
                As[kk + 3][r] = fmaxf(di * ag.w + bb.w, 0.f);
            }
        }
#pragma unroll
        for (int t = 0; t < 2; t++) {   // B tile: 16 k x 64 cols
            int fi = tid + t * 128;
            int kk = fi >> 4, c4 = (fi & 15) << 2;
            *(float4*)&Bs[kk][c4] = *(const float4*)(W2 + (size_t)(k0 + kk) * CO + c4);
        }
        __syncthreads();
#pragma unroll
        for (int kk = 0; kk < 16; kk++) {
            int ra = warp * 16 + sub * 8;
            float4 a0 = *(const float4*)&As[kk][ra];
            float4 a1 = *(const float4*)&As[kk][ra + 4];
            float4 b  = *(const float4*)&Bs[kk][cg * 4];
            float av[8] = {a0.x, a0.y, a0.z, a0.w, a1.x, a1.y, a1.z, a1.w};
#pragma unroll
            for (int r = 0; r < 8; r++) {
                acc[r][0] += av[r] * b.x;
                acc[r][1] += av[r] * b.y;
                acc[r][2] += av[r] * b.z;
                acc[r][3] += av[r] * b.w;
            }
        }
        __syncthreads();
    }
#pragma unroll
    for (int r = 0; r < 8; r++) {
        int gr = row0 + warp * 16 + sub * 8 + r;
        if (gr >= NN) continue;
        float di = g_dinv[gr];
        float4 u = make_float4(acc[r][0] * di, acc[r][1] * di,
                               acc[r][2] * di, acc[r][3] * di);
        size_t off = (size_t)gr * CO + cg * 4;
        *(float4*)(g_u2 + off)  = u;
        *(float4*)(agg2 + off)  = make_float4(2.f * u.x, 2.f * u.y,
                                              2.f * u.z, 2.f * u.w);
    }
}

// ---------------- scatter layer 2: agg2[d] += u2[s] (half-warp / edge) -----
__global__ __launch_bounds__(256) void k_scatter2(const int* __restrict__ ei,
                                                  float* __restrict__ agg2) {
    int gw = (blockIdx.x * 256 + threadIdx.x) >> 5;
    int lane = threadIdx.x & 31;
    int e = gw * 2 + (lane >> 4);
    if (e >= NE) return;
    int li = lane & 15;
    int is64 = g_is64;
    int s = edge_val(ei, e, is64);
    int d = edge_val(ei, NE + e, is64);
    const float4 u = *(const float4*)(g_u2 + (size_t)s * CO + li * 4);
    float* p = agg2 + (size_t)d * CO + li * 4;
    asm volatile("red.global.add.v4.f32 [%0], {%1,%2,%3,%4};"
                 :: "l"(p), "f"(u.x), "f"(u.y), "f"(u.z), "f"(u.w)
                 : "memory");
}

// ---------------- final: v = dinv*agg2 + b2 ; log_softmax (in place) -------
__global__ __launch_bounds__(256) void k_final(const float* __restrict__ b2,
                                               float* __restrict__ out) {
    int warp = threadIdx.x >> 5, lane = threadIdx.x & 31;
    int node = blockIdx.x * 8 + warp;
    if (node >= NN) return;
    float di = g_dinv[node];
    float2 a  = *(const float2*)(out + (size_t)node * CO + lane * 2);
    float2 bb = *(const float2*)(b2 + lane * 2);
    float v0 = di * a.x + bb.x;
    float v1 = di * a.y + bb.y;
    float m = fmaxf(v0, v1);
#pragma unroll
    for (int o = 16; o > 0; o >>= 1)
        m = fmaxf(m, __shfl_xor_sync(0xffffffffu, m, o));
    float s = expf(v0 - m) + expf(v1 - m);
#pragma unroll
    for (int o = 16; o > 0; o >>= 1)
        s += __shfl_xor_sync(0xffffffffu, s, o);
    float l = m + logf(s);
    *(float2*)(out + (size_t)node * CO + lane * 2) = make_float2(v0 - l, v1 - l);
}

// ---------------- launch ----------------------------------------------------
extern "C" void kernel_launch(void* const* d_in, const int* in_sizes, int n_in,
                              void* d_out, int out_size) {
    const float* x  = (const float*)d_in[0];
    const int*   ei = (const int*)d_in[1];   // int32 or int64 (detected on device)
    const float* W1 = (const float*)d_in[2];
    const float* b1 = (const float*)d_in[3];
    const float* W2 = (const float*)d_in[4];
    const float* b2 = (const float*)d_in[5];
    float* out = (float*)d_out;

    k_init<<<(NN + 255) / 256, 256>>>(ei);
    k_deg<<<(NE + 255) / 256, 256>>>(ei);
    k_dinv<<<(NN + 255) / 256, 256>>>();
    k_gemm1<<<(NN + 63) / 64, 256>>>(x, W1);
    k_scatter1<<<NE / 8, 256>>>(ei);                 // 8 warps/block, warp/edge
    k_gemm2<<<(NN + 63) / 64, 128>>>(b1, W2, out);
    k_scatter2<<<NE / 16, 256>>>(ei, out);           // half-warp/edge
    k_final<<<(NN + 7) / 8, 256>>>(b2, out);
}

// round 16
// speedup vs baseline: 1.0002x; 1.0002x over previous
#include <cuda_runtime.h>

#define NN 100000
#define NE 1600000
#define CIN 128
#define CH  128
#define CO  64

// ---------------- scratch (device globals: allocation-free) ----------------
__device__ __align__(16) float g_u1[(size_t)NN * CH];    // (x@W1)*dinv[row]
__device__ __align__(16) float g_agg1[(size_t)NN * CH];  // layer-1 accumulator
__device__ __align__(16) float g_u2[(size_t)NN * CO];    // (x2@W2)*dinv[row]
__device__ int   g_deg[NN];
__device__ float g_dinv[NN];
__device__ int   g_is64;   // 1 if edge_index is int64, 0 if int32

// ---------------- init: zero degrees + detect edge dtype -------------------
__global__ void k_init(const int* __restrict__ ei) {
    int i = blockIdx.x * blockDim.x + threadIdx.x;
    if (i < NN) g_deg[i] = 0;
    if (blockIdx.x == 0) {
        __shared__ int s_nz;
        if (threadIdx.x == 0) s_nz = 0;
        __syncthreads();
        // If int64 with values in [0,100000): every odd int32 word is 0.
        // If int32: odd words are random edge ids (P(all 256 == 0) ~ 0).
        if (ei[2 * threadIdx.x + 1] != 0) atomicOr(&s_nz, 1);
        __syncthreads();
        if (threadIdx.x == 0) g_is64 = s_nz ? 0 : 1;
    }
}

__device__ __forceinline__ int edge_val(const int* ei, int idx, int is64) {
    if (is64) return (int)((const long long*)ei)[idx];
    return ei[idx];
}

// ---------------- degree histogram over dst ---------------------------------
__global__ void k_deg(const int* __restrict__ ei) {
    int e = blockIdx.x * blockDim.x + threadIdx.x;
    if (e >= NE) return;
    int is64 = g_is64;
    int d = edge_val(ei, NE + e, is64);
    atomicAdd(&g_deg[d], 1);
}

__global__ void k_dinv() {
    int i = blockIdx.x * blockDim.x + threadIdx.x;
    if (i < NN) g_dinv[i] = rsqrtf((float)(g_deg[i] + 2));  // +2 self loops
}

// ---------------- GEMM1: u1 = (x @ W1) * dinv ; agg1 = 2*u1 ----------------
// 64 rows x 128 cols per block, 256 threads, thread = 8 rows x 4 cols.
__global__ __launch_bounds__(256) void k_gemm1(const float* __restrict__ x,
                                               const float* __restrict__ W) {
    __shared__ float As[16][64];    // k-major (transposed) A tile
    __shared__ float Bs[16][128];
    int row0 = blockIdx.x * 64;
    int tid  = threadIdx.x;
    int warp = tid >> 5, lane = tid & 31;

    float acc[8][4];
#pragma unroll
    for (int r = 0; r < 8; r++)
#pragma unroll
        for (int c = 0; c < 4; c++) acc[r][c] = 0.f;

    for (int k0 = 0; k0 < CIN; k0 += 16) {
        {   // A tile: 64 rows x 16 k
            int r = tid >> 2, kk4 = (tid & 3) << 2;
            int gr = row0 + r;
            float4 a = make_float4(0.f, 0.f, 0.f, 0.f);
            if (gr < NN) a = *(const float4*)(x + (size_t)gr * CIN + k0 + kk4);
            As[kk4 + 0][r] = a.x; As[kk4 + 1][r] = a.y;
            As[kk4 + 2][r] = a.z; As[kk4 + 3][r] = a.w;
        }
#pragma unroll
        for (int t = 0; t < 2; t++) {   // B tile: 16 k x 128 cols
            int fi = tid + t * 256;
            int kk = fi >> 5, c4 = (fi & 31) << 2;
            *(float4*)&Bs[kk][c4] = *(const float4*)(W + (size_t)(k0 + kk) * CH + c4);
        }
        __syncthreads();
#pragma unroll
        for (int kk = 0; kk < 16; kk++) {
            float4 a0 = *(const float4*)&As[kk][warp * 8];
            float4 a1 = *(const float4*)&As[kk][warp * 8 + 4];
            float4 b  = *(const float4*)&Bs[kk][lane * 4];
            float av[8] = {a0.x, a0.y, a0.z, a0.w, a1.x, a1.y, a1.z, a1.w};
#pragma unroll
            for (int r = 0; r < 8; r++) {
                acc[r][0] += av[r] * b.x;
                acc[r][1] += av[r] * b.y;
                acc[r][2] += av[r] * b.z;
                acc[r][3] += av[r] * b.w;
            }
        }
        __syncthreads();
    }
#pragma unroll
    for (int r = 0; r < 8; r++) {
        int gr = row0 + warp * 8 + r;
        if (gr >= NN) continue;
        float di = g_dinv[gr];
        float4 u = make_float4(acc[r][0] * di, acc[r][1] * di,
                               acc[r][2] * di, acc[r][3] * di);
        size_t off = (size_t)gr * CH + lane * 4;
        *(float4*)(g_u1 + off)   = u;
        *(float4*)(g_agg1 + off) = make_float4(2.f * u.x, 2.f * u.y,
                                               2.f * u.z, 2.f * u.w);
    }
}

// ---------------- scatter layer 1: agg1[d] += u1[s] (one warp / edge) ------
__global__ __launch_bounds__(256) void k_scatter1(const int* __restrict__ ei) {
    int gw = (blockIdx.x * 256 + threadIdx.x) >> 5;
    if (gw >= NE) return;
    int lane = threadIdx.x & 31;
    int is64 = g_is64;
    int s = edge_val(ei, gw, is64);
    int d = edge_val(ei, NE + gw, is64);
    const float4 u = *(const float4*)(g_u1 + (size_t)s * CH + lane * 4);
    float* p = g_agg1 + (size_t)d * CH + lane * 4;
    asm volatile("red.global.add.v4.f32 [%0], {%1,%2,%3,%4};"
                 :: "l"(p), "f"(u.x), "f"(u.y), "f"(u.z), "f"(u.w)
                 : "memory");
}

// ---------------- GEMM2: x2 = relu(dinv*agg1 + b1) fused into A-load -------
// u2 = (x2 @ W2) * dinv ; agg2(=d_out) = 2*u2.
// 64 rows x 64 cols per block, 128 threads, thread = 8 rows x 4 cols.
__global__ __launch_bounds__(128) void k_gemm2(const float* __restrict__ b1,
                                               const float* __restrict__ W2,
                                               float* __restrict__ agg2) {
    __shared__ float As[16][64];
    __shared__ float Bs[16][64];
    int row0 = blockIdx.x * 64;
    int tid  = threadIdx.x;
    int warp = tid >> 5, lane = tid & 31;
    int sub = lane >> 4, cg = lane & 15;

    float acc[8][4];
#pragma unroll
    for (int r = 0; r < 8; r++)
#pragma unroll
        for (int c = 0; c < 4; c++) acc[r][c] = 0.f;

    for (int k0 = 0; k0 < CH; k0 += 16) {
        {   // A tile with fused relu(dinv*agg1 + b1)
            int r = tid >> 1, kh = (tid & 1) << 3;
            int gr = row0 + r;
            float di = (gr < NN) ? g_dinv[gr] : 0.f;
#pragma unroll
            for (int t = 0; t < 2; t++) {
                int kk = kh + t * 4;
                float4 ag = make_float4(0.f, 0.f, 0.f, 0.f);
                if (gr < NN) ag = *(const float4*)(g_agg1 + (size_t)gr * CH + k0 + kk);
                float4 bb = *(const float4*)(b1 + k0 + kk);
                As[kk + 0][r] = fmaxf(di * ag.x + bb.x, 0.f);
                As[kk + 1][r] = fmaxf(di * ag.y + bb.y, 0.f);
                As[kk + 2][r] = fmaxf(di * ag.z + bb.z, 0.f);
                As[kk + 3][r] = fmaxf(di * ag.w + bb.w, 0.f);
            }
        }
#pragma unroll
        for (int t = 0; t < 2; t++) {   // B tile: 16 k x 64 cols
            int fi = tid + t * 128;
            int kk = fi >> 4, c4 = (fi & 15) << 2;
            *(float4*)&Bs[kk][c4] = *(const float4*)(W2 + (size_t)(k0 + kk) * CO + c4);
        }
        __syncthreads();
#pragma unroll
        for (int kk = 0; kk < 16; kk++) {
            int ra = warp * 16 + sub * 8;
            float4 a0 = *(const float4*)&As[kk][ra];
            float4 a1 = *(const float4*)&As[kk][ra + 4];
            float4 b  = *(const float4*)&Bs[kk][cg * 4];
            float av[8] = {a0.x, a0.y, a0.z, a0.w, a1.x, a1.y, a1.z, a1.w};
#pragma unroll
            for (int r = 0; r < 8; r++) {
                acc[r][0] += av[r] * b.x;
                acc[r][1] += av[r] * b.y;
                acc[r][2] += av[r] * b.z;
                acc[r][3] += av[r] * b.w;
            }
        }
        __syncthreads();
    }
#pragma unroll
    for (int r = 0; r < 8; r++) {
        int gr = row0 + warp * 16 + sub * 8 + r;
        if (gr >= NN) continue;
        float di = g_dinv[gr];
        float4 u = make_float4(acc[r][0] * di, acc[r][1] * di,
                               acc[r][2] * di, acc[r][3] * di);
        size_t off = (size_t)gr * CO + cg * 4;
        *(float4*)(g_u2 + off)  = u;
        *(float4*)(agg2 + off)  = make_float4(2.f * u.x, 2.f * u.y,
                                              2.f * u.z, 2.f * u.w);
    }
}

// ---------------- scatter layer 2: agg2[d] += u2[s] (half-warp / edge) -----
__global__ __launch_bounds__(256) void k_scatter2(const int* __restrict__ ei,
                                                  float* __restrict__ agg2) {
    int gw = (blockIdx.x * 256 + threadIdx.x) >> 5;
    int lane = threadIdx.x & 31;
    int e = gw * 2 + (lane >> 4);
    if (e >= NE) return;
    int li = lane & 15;
    int is64 = g_is64;
    int s = edge_val(ei, e, is64);
    int d = edge_val(ei, NE + e, is64);
    const float4 u = *(const float4*)(g_u2 + (size_t)s * CO + li * 4);
    float* p = agg2 + (size_t)d * CO + li * 4;
    asm volatile("red.global.add.v4.f32 [%0], {%1,%2,%3,%4};"
                 :: "l"(p), "f"(u.x), "f"(u.y), "f"(u.z), "f"(u.w)
                 : "memory");
}

// ---------------- final: v = dinv*agg2 + b2 ; log_softmax (in place) -------
__global__ __launch_bounds__(256) void k_final(const float* __restrict__ b2,
                                               float* __restrict__ out) {
    int warp = threadIdx.x >> 5, lane = threadIdx.x & 31;
    int node = blockIdx.x * 8 + warp;
    if (node >= NN) return;
    float di = g_dinv[node];
    float2 a  = *(const float2*)(out + (size_t)node * CO + lane * 2);
    float2 bb = *(const float2*)(b2 + lane * 2);
    float v0 = di * a.x + bb.x;
    float v1 = di * a.y + bb.y;
    float m = fmaxf(v0, v1);
#pragma unroll
    for (int o = 16; o > 0; o >>= 1)
        m = fmaxf(m, __shfl_xor_sync(0xffffffffu, m, o));
    float s = expf(v0 - m) + expf(v1 - m);
#pragma unroll
    for (int o = 16; o > 0; o >>= 1)
        s += __shfl_xor_sync(0xffffffffu, s, o);
    float l = m + logf(s);
    *(float2*)(out + (size_t)node * CO + lane * 2) = make_float2(v0 - l, v1 - l);
}

// ---------------- launch ----------------------------------------------------
extern "C" void kernel_launch(void* const* d_in, const int* in_sizes, int n_in,
                              void* d_out, int out_size) {
    const float* x  = (const float*)d_in[0];
    const int*   ei = (const int*)d_in[1];   // int32 or int64 (detected on device)
    const float* W1 = (const float*)d_in[2];
    const float* b1 = (const float*)d_in[3];
    const float* W2 = (const float*)d_in[4];
    const float* b2 = (const float*)d_in[5];
    float* out = (float*)d_out;

    k_init<<<(NN + 255) / 256, 256>>>(ei);
    k_deg<<<(NE + 255) / 256, 256>>>(ei);
    k_dinv<<<(NN + 255) / 256, 256>>>();
    k_gemm1<<<(NN + 63) / 64, 256>>>(x, W1);
    k_scatter1<<<NE / 8, 256>>>(ei);                 // 8 warps/block, warp/edge
    k_gemm2<<<(NN + 63) / 64, 128>>>(b1, W2, out);
    k_scatter2<<<NE / 16, 256>>>(ei, out);           // half-warp/edge
    k_final<<<(NN + 7) / 8, 256>>>(b2, out);
}